// round 1
// baseline (speedup 1.0000x reference)
#include <cuda_runtime.h>
#include <cstdint>

#define NT 8192
#define ND 2048
#define NE 16
#define CAP 512   // NT / NE

// ---------------- scratch (no allocations allowed) ----------------
__device__ float g_probs[NT * NE];               // softmax probs per token
__device__ unsigned long long g_prefs[NT];       // packed expert-preference order (16 nibbles)

// =====================================================================
// Kernel 1: affinities GEMV + softmax + preference-order packing
//   each warp computes 2 tokens; lanes split K with float4 loads
// =====================================================================
__global__ void __launch_bounds__(256) gemv_kernel(const float* __restrict__ f,
                                                   const float* __restrict__ W,
                                                   const float* __restrict__ b) {
    const int wid  = threadIdx.x >> 5;
    const int lane = threadIdx.x & 31;
    const int warp = blockIdx.x * 8 + wid;
    const int t0   = warp * 2;

    const float4* f0 = reinterpret_cast<const float4*>(f + (size_t)t0 * ND);
    const float4* f1 = reinterpret_cast<const float4*>(f + (size_t)(t0 + 1) * ND);
    const float4* W4 = reinterpret_cast<const float4*>(W);

    float acc0[NE], acc1[NE];
#pragma unroll
    for (int e = 0; e < NE; ++e) { acc0[e] = 0.f; acc1[e] = 0.f; }

#pragma unroll 2
    for (int i = 0; i < ND / 128; ++i) {     // 16 iterations
        const int k4 = i * 32 + lane;        // float4 index into the row
        const float4 a0 = f0[k4];
        const float4 a1 = f1[k4];
#pragma unroll
        for (int e = 0; e < NE; ++e) {
            const float4 w = __ldg(W4 + e * (ND / 4) + k4);
            acc0[e] = fmaf(a0.x, w.x, acc0[e]);
            acc0[e] = fmaf(a0.y, w.y, acc0[e]);
            acc0[e] = fmaf(a0.z, w.z, acc0[e]);
            acc0[e] = fmaf(a0.w, w.w, acc0[e]);
            acc1[e] = fmaf(a1.x, w.x, acc1[e]);
            acc1[e] = fmaf(a1.y, w.y, acc1[e]);
            acc1[e] = fmaf(a1.z, w.z, acc1[e]);
            acc1[e] = fmaf(a1.w, w.w, acc1[e]);
        }
    }

    // warp reduction: afterwards every lane holds full sums
#pragma unroll
    for (int e = 0; e < NE; ++e) {
        float v0 = acc0[e], v1 = acc1[e];
#pragma unroll
        for (int o = 16; o; o >>= 1) {
            v0 += __shfl_xor_sync(0xFFFFFFFFu, v0, o);
            v1 += __shfl_xor_sync(0xFFFFFFFFu, v1, o);
        }
        acc0[e] = v0; acc1[e] = v1;
    }

    if (lane < 2) {
        const int t = t0 + lane;
        float aff[NE];
#pragma unroll
        for (int e = 0; e < NE; ++e)
            aff[e] = (lane ? acc1[e] : acc0[e]) + __ldg(b + e);

        // softmax (matches jax.nn.softmax: exp(a - max) / sum)
        float m = aff[0];
#pragma unroll
        for (int e = 1; e < NE; ++e) m = fmaxf(m, aff[e]);
        float p[NE]; float s = 0.f;
#pragma unroll
        for (int e = 0; e < NE; ++e) { p[e] = expf(aff[e] - m); s += p[e]; }
        const float inv = 1.f / s;
#pragma unroll
        for (int e = 0; e < NE; ++e) g_probs[t * NE + e] = p[e] * inv;

        // strict sort keys: descending score, tie -> lower expert index first
        unsigned long long key[NE];
#pragma unroll
        for (int e = 0; e < NE; ++e) {
            unsigned u = __float_as_uint(aff[e]);
            u = (u & 0x80000000u) ? ~u : (u | 0x80000000u);
            key[e] = (1ull << 40) | ((unsigned long long)u << 4)
                   | (unsigned long long)(NE - 1 - e);
        }
        unsigned used = 0;
        unsigned long long pref = 0;
#pragma unroll
        for (int i = 0; i < NE; ++i) {
            int best = 0; unsigned long long bk = 0;
#pragma unroll
            for (int e = 0; e < NE; ++e) {
                const bool take = !((used >> e) & 1u) && key[e] > bk;
                bk   = take ? key[e] : bk;
                best = take ? e      : best;
            }
            used |= 1u << best;
            pref |= ((unsigned long long)best) << (4 * i);
        }
        g_prefs[t] = pref;
    }
}

// =====================================================================
// Kernel 2: phased balanced assignment + stable counting sort + gather
//   single 1024-thread block; preference words staged in smem
// =====================================================================

// block-wide exclusive scan of 16 counters packed as 4 x u64 (16-bit lanes)
__device__ __forceinline__ void block_excl_scan16(const unsigned long long cnt[4],
                                                  unsigned long long pre[4],
                                                  unsigned long long* s_wscan,
                                                  int lane, int wid) {
    unsigned long long incl[4];
#pragma unroll
    for (int c = 0; c < 4; ++c) incl[c] = cnt[c];
#pragma unroll
    for (int o = 1; o < 32; o <<= 1) {
#pragma unroll
        for (int c = 0; c < 4; ++c) {
            unsigned long long v = __shfl_up_sync(0xFFFFFFFFu, incl[c], o);
            if (lane >= o) incl[c] += v;
        }
    }
    if (lane == 31) {
#pragma unroll
        for (int c = 0; c < 4; ++c) s_wscan[wid * 4 + c] = incl[c];
    }
    __syncthreads();
    if (wid == 0) {
        unsigned long long tot[4], in2[4];
#pragma unroll
        for (int c = 0; c < 4; ++c) { tot[c] = s_wscan[lane * 4 + c]; in2[c] = tot[c]; }
#pragma unroll
        for (int o = 1; o < 32; o <<= 1) {
#pragma unroll
            for (int c = 0; c < 4; ++c) {
                unsigned long long v = __shfl_up_sync(0xFFFFFFFFu, in2[c], o);
                if (lane >= o) in2[c] += v;
            }
        }
#pragma unroll
        for (int c = 0; c < 4; ++c) s_wscan[lane * 4 + c] = in2[c] - tot[c];
    }
    __syncthreads();
#pragma unroll
    for (int c = 0; c < 4; ++c) pre[c] = s_wscan[wid * 4 + c] + incl[c] - cnt[c];
}

#define SMEM_PREF   0
#define SMEM_CHOICE 65536
#define SMEM_WSCAN  (65536 + 8192)
#define SMEM_INT    (65536 + 8192 + 1024)
#define SMEM_BYTES  (65536 + 8192 + 1024 + 128)
// s_int layout: [0..15] caps, [16] active mask, [17] start pos, [18] atomicMin slot

__global__ void __launch_bounds__(1024) assign_kernel(float* __restrict__ out,
                                                      int out_size) {
    extern __shared__ unsigned char smem[];
    unsigned long long* s_pref   = (unsigned long long*)(smem + SMEM_PREF);
    unsigned char*      s_choice = (unsigned char*)(smem + SMEM_CHOICE);
    unsigned long long* s_wscan  = (unsigned long long*)(smem + SMEM_WSCAN);
    int*                s_int    = (int*)(smem + SMEM_INT);

    const int tid  = threadIdx.x;
    const int lane = tid & 31;
    const int wid  = tid >> 5;

    for (int i = tid; i < NT; i += 1024) s_pref[i] = g_prefs[i];
    if (tid < NE) s_int[tid] = CAP;
    if (tid == 0) { s_int[16] = 0xFFFF; s_int[17] = 0; }
    __syncthreads();

    // ---------------- phase loop (<= 17 iterations) ----------------
    for (int phase = 0; phase <= NE; ++phase) {
        const int s = s_int[17];
        if (s >= NT) break;
        const int active = s_int[16];
        const int n      = NT - s;
        const int chunk  = (n + 1023) >> 10;
        const int c0     = s + tid * chunk;
        const int c1     = min(c0 + chunk, NT);
        if (tid == 0) s_int[18] = 0x7FFFFFFF;

        // choices under current mask + local per-expert counts (packed u16x16)
        unsigned long long cnt[4] = {0, 0, 0, 0};
        for (int t = c0; t < c1; ++t) {
            unsigned long long p = s_pref[t];
            int c = (int)(p & 0xF);
            while (!((active >> c) & 1)) { p >>= 4; c = (int)(p & 0xF); }
            s_choice[t] = (unsigned char)c;
            cnt[c >> 2] += 1ull << ((c & 3) << 4);
        }

        unsigned long long pre[4];
        block_excl_scan16(cnt, pre, s_wscan, lane, wid);   // syncs inside

        // find first saturation position across all active experts
#pragma unroll
        for (int e = 0; e < NE; ++e) {
            if (!((active >> e) & 1)) continue;
            const int pe   = (int)((pre[e >> 2] >> ((e & 3) << 4)) & 0xFFFF);
            const int ce   = (int)((cnt[e >> 2] >> ((e & 3) << 4)) & 0xFFFF);
            const int cape = s_int[e];
            if (pe < cape && pe + ce >= cape) {
                int need = cape - pe;
                int pos  = -1;
                for (int t = c0; t < c1; ++t) {
                    if (s_choice[t] == (unsigned char)e) {
                        if (--need == 0) { pos = t; break; }
                    }
                }
                atomicMin(&s_int[18], (pos << 4) | e);
            }
        }
        __syncthreads();

        const int mv = s_int[18];
        if (mv == 0x7FFFFFFF) {
            if (tid == 0) s_int[17] = NT;   // no saturation: everything finalized
        } else {
            const int pstar = mv >> 4;
            const int estar = mv & 0xF;
            if (pstar >= c0 && pstar < c1) {        // unique owner thread
                int loc[NE];
#pragma unroll
                for (int e = 0; e < NE; ++e) loc[e] = 0;
                for (int t = c0; t <= pstar; ++t) loc[s_choice[t]]++;
#pragma unroll
                for (int e = 0; e < NE; ++e) {
                    if ((active >> e) & 1) {
                        const int pe = (int)((pre[e >> 2] >> ((e & 3) << 4)) & 0xFFFF);
                        s_int[e] -= pe + loc[e];
                    }
                }
                s_int[16] = active & ~(1 << estar);
                s_int[17] = pstar + 1;
            }
        }
        __syncthreads();
    }

    // ---------------- stable counting sort + gather + output ----------------
    {
        const int base = tid * 8;
        unsigned long long cnt[4] = {0, 0, 0, 0};
        unsigned char ch[8];
#pragma unroll
        for (int i = 0; i < 8; ++i) {
            const int e = s_choice[base + i];
            ch[i] = (unsigned char)e;
            cnt[e >> 2] += 1ull << ((e & 3) << 4);
        }
        unsigned long long pre[4];
        block_excl_scan16(cnt, pre, s_wscan, lane, wid);

#pragma unroll
        for (int i = 0; i < 8; ++i) {
            const int e    = ch[i];
            const int rank = (int)((pre[e >> 2] >> ((e & 3) << 4)) & 0xFFFF);
            const int pos  = e * CAP + rank;
            if (pos < out_size) out[pos] = (float)(base + i);
            const int gi = NT + base + i;
            if (gi < out_size) out[gi] = g_probs[(base + i) * NE + e];
            pre[e >> 2] += 1ull << ((e & 3) << 4);
        }
    }
}

// =====================================================================
extern "C" void kernel_launch(void* const* d_in, const int* in_sizes, int n_in,
                              void* d_out, int out_size) {
    const float* f = (const float*)d_in[0];   // features [8192, 2048] f32
    const float* W = (const float*)d_in[1];   // gate weight [16, 2048] f32
    const float* b = (const float*)d_in[2];   // bias [16] f32
    float* out = (float*)d_out;               // [8192] sort_by_expert ++ [8192] gathered

    gemv_kernel<<<NT / 16, 256>>>(f, W, b);

    cudaFuncSetAttribute(assign_kernel,
                         cudaFuncAttributeMaxDynamicSharedMemorySize, SMEM_BYTES);
    assign_kernel<<<1, 1024, SMEM_BYTES>>>(out, out_size);
}